// round 16
// baseline (speedup 1.0000x reference)
#include <cuda_runtime.h>
#include <cstdint>

#define NN   4096
#define IN_F 256
#define HD   512
#define NH   8
#define DD   64
#define NT   (NN / 32)     // 128 j-tiles

// Scratch (no allocations allowed)
__device__ float g_h[NN * HD];            // h = inp @ W^T   [N, H*D]
__device__ float g_e1[NH * NN];           // exp(s[h][n])
__device__ float g_e2[NH * NN];           // exp(0.2*s[h][n])
__device__ unsigned char g_amask[32 * NT];// per (i-tile 128 x j-tile 32): any A != 0

__device__ __forceinline__ float to_tf32(float x) {
    float r;
    asm("cvt.rna.tf32.f32 %0, %1;" : "=f"(r) : "f"(x));
    return r;
}

__device__ __forceinline__ void mma_tf32(float* c, const uint32_t* a, const uint32_t* b) {
    asm volatile(
        "mma.sync.aligned.m16n8k8.row.col.f32.tf32.tf32.f32 "
        "{%0,%1,%2,%3}, {%4,%5,%6,%7}, {%8,%9}, {%0,%1,%2,%3};"
        : "+f"(c[0]), "+f"(c[1]), "+f"(c[2]), "+f"(c[3])
        : "r"(a[0]), "r"(a[1]), "r"(a[2]), "r"(a[3]), "r"(b[0]), "r"(b[1]));
}

__device__ __forceinline__ void cp_async16(uint32_t smem_addr, const void* gptr) {
    asm volatile("cp.async.ca.shared.global [%0], [%1], 16;"
                 :: "r"(smem_addr), "l"(gptr) : "memory");
}
__device__ __forceinline__ void cp_commit() {
    asm volatile("cp.async.commit_group;" ::: "memory");
}
__device__ __forceinline__ void cp_wait0() {
    asm volatile("cp.async.wait_group 0;" ::: "memory");
}
__device__ __forceinline__ uint32_t smem_u32(const void* p) {
    uint32_t a;
    asm("{ .reg .u64 t; cvta.to.shared.u64 t, %1; cvt.u32.u64 %0, t; }"
        : "=r"(a) : "l"(p));
    return a;
}

// ---------------------------------------------------------------------------
// Kernel 1: h = inp @ W^T.  BM=64, BN=32, BK=16, 128 threads, 4x4 micro-tile.
// ---------------------------------------------------------------------------
__global__ __launch_bounds__(128) void gemm_h_kernel(
    const float* __restrict__ inp, const float* __restrict__ W)
{
    __shared__ float smA[16][64];
    __shared__ float smB[16][32];
    const int tid = threadIdx.x;
    const int m0 = blockIdx.y * 64;
    const int n0 = blockIdx.x * 32;
    const int tx = tid & 7;
    const int ty = tid >> 3;

    float acc[4][4];
#pragma unroll
    for (int r = 0; r < 4; r++)
#pragma unroll
        for (int c = 0; c < 4; c++) acc[r][c] = 0.f;

    for (int k0 = 0; k0 < IN_F; k0 += 16) {
#pragma unroll
        for (int p = 0; p < 2; p++) {
            int idx = p * 128 + tid;
            int r = idx >> 2, q = idx & 3;
            float4 v = *(const float4*)&inp[(size_t)(m0 + r) * IN_F + k0 + 4 * q];
            smA[4 * q + 0][r] = v.x; smA[4 * q + 1][r] = v.y;
            smA[4 * q + 2][r] = v.z; smA[4 * q + 3][r] = v.w;
        }
        {
            int r = tid >> 2, q = tid & 3;
            float4 v = *(const float4*)&W[(size_t)(n0 + r) * IN_F + k0 + 4 * q];
            smB[4 * q + 0][r] = v.x; smB[4 * q + 1][r] = v.y;
            smB[4 * q + 2][r] = v.z; smB[4 * q + 3][r] = v.w;
        }
        __syncthreads();
#pragma unroll
        for (int k = 0; k < 16; k++) {
            float4 a4 = *(const float4*)&smA[k][ty * 4];
            float4 b4 = *(const float4*)&smB[k][tx * 4];
            float a[4] = {a4.x, a4.y, a4.z, a4.w};
            float b[4] = {b4.x, b4.y, b4.z, b4.w};
#pragma unroll
            for (int r = 0; r < 4; r++)
#pragma unroll
                for (int c = 0; c < 4; c++) acc[r][c] += a[r] * b[c];
        }
        __syncthreads();
    }
#pragma unroll
    for (int r = 0; r < 4; r++) {
        float4 v = make_float4(acc[r][0], acc[r][1], acc[r][2], acc[r][3]);
        *(float4*)&g_h[(size_t)(m0 + ty * 4 + r) * HD + n0 + tx * 4] = v;
    }
}

// ---------------------------------------------------------------------------
// Kernel 2: scores -> exp tables. One warp per (n,h).
// ---------------------------------------------------------------------------
__global__ __launch_bounds__(256) void scores_kernel(const float* __restrict__ a_left)
{
    int gid  = blockIdx.x * 8 + (threadIdx.x >> 5);
    int lane = threadIdx.x & 31;
    int h = gid & 7;
    int n = gid >> 3;
    float2 v = *(const float2*)&g_h[(size_t)n * HD + h * DD + lane * 2];
    float2 a = *(const float2*)&a_left[h * DD + lane * 2];
    float p = v.x * a.x + v.y * a.y;
#pragma unroll
    for (int o = 16; o > 0; o >>= 1) p += __shfl_xor_sync(0xffffffffu, p, o);
    if (lane == 0) {
        g_e1[h * NN + n] = __expf(p);
        g_e2[h * NN + n] = __expf(0.2f * p);
    }
}

// ---------------------------------------------------------------------------
// Kernel 2b: A nonzero mask per (i-tile 128 x j-tile 32).
// ---------------------------------------------------------------------------
__global__ __launch_bounds__(256) void amask_kernel(const float* __restrict__ A)
{
    const int it = blockIdx.y, jt = blockIdx.x;
    const int tid = threadIdx.x;
    const float* base = A + (size_t)it * 128 * NN + jt * 32;
    int any = 0;
#pragma unroll
    for (int rr = 0; rr < 4; rr++) {
        int row = rr * 32 + (tid >> 3);
        float4 v = *(const float4*)(base + (size_t)row * NN + (tid & 7) * 4);
        any |= (v.x != 0.f) | (v.y != 0.f) | (v.z != 0.f) | (v.w != 0.f);
    }
    int r = __syncthreads_or(any);
    if (tid == 0) g_amask[it * NT + jt] = (unsigned char)(r ? 1 : 0);
}

// ---------------------------------------------------------------------------
// Kernel 3: attention via tf32 mma.sync, register-resident weight fragments.
// Grid (64, 8) = 512 CTAs (~3.46/SM), 128 threads (4 warps, each m16 x n64),
// 4 CTAs/SM -> barrier stalls hidden by other resident CTAs.
//  - V tile double-buffered in smem via cp.async (raw fp32; HW tf32 truncation)
//  - A-fragments in registers: w = tf32(max(e1i*e1j, e2i*e2j)); rare path *exp(A)
//  - one __syncthreads + one wait_group per tile
// ---------------------------------------------------------------------------
__global__ __launch_bounds__(128, 4) void attn_kernel(
    const float* __restrict__ Amat, float* __restrict__ out)
{
    __shared__ float Vt[2][32][72];       // [buf][k][d], pad 72 -> conflict-free B-frag LDS
    __shared__ unsigned char smask[NT];

    const int tid  = threadIdx.x;
    const int lane = tid & 31;
    const int wid  = tid >> 5;            // 0..3
    const int g    = lane >> 2;           // 0..7
    const int t    = lane & 3;            // 0..3
    const int h    = blockIdx.y;
    const int i0   = blockIdx.x * 64;

    smask[tid] = g_amask[(blockIdx.x >> 1) * NT + tid];

    const int ra = wid * 16 + g;
    const int rb = ra + 8;
    const float e1A = g_e1[h * NN + i0 + ra], e2A = g_e2[h * NN + i0 + ra];
    const float e1B = g_e1[h * NN + i0 + rb], e2B = g_e2[h * NN + i0 + rb];

    float dA = 0.f, dB = 0.f;
    float acc[8][4];
#pragma unroll
    for (int n = 0; n < 8; n++)
#pragma unroll
        for (int c = 0; c < 4; c++) acc[n][c] = 0.f;

    // V fill via cp.async: thread handles row vj = tid>>2, 16 floats at (tid&3)*16
    const int vj = tid >> 2, vq = (tid & 3) * 16;
    const uint32_t vdst0 = smem_u32(&Vt[0][vj][vq]);
    const uint32_t vdst1 = smem_u32(&Vt[1][vj][vq]);

    // prefetch tile 0
    {
        const float* src = &g_h[(size_t)vj * HD + h * DD + vq];
        cp_async16(vdst0,      src);
        cp_async16(vdst0 + 16, src + 4);
        cp_async16(vdst0 + 32, src + 8);
        cp_async16(vdst0 + 48, src + 12);
        cp_commit();
    }

    for (int it = 0; it < NT; ++it) {
        const int s  = it & 1;
        const int j0 = it * 32;

        cp_wait0();          // tile it landed (it+1 not yet issued)
        __syncthreads();     // visible to all; prior reads of buf s done by all warps

        // prefetch next tile into the other buffer (runs during compute below)
        if (it + 1 < NT) {
            const float* src = &g_h[(size_t)(j0 + 32 + vj) * HD + h * DD + vq];
            const uint32_t d = s ? vdst0 : vdst1;
            cp_async16(d,      src);
            cp_async16(d + 16, src + 4);
            cp_async16(d + 32, src + 8);
            cp_async16(d + 48, src + 12);
            cp_commit();
        }

        // j exponentials for this thread's 8 k-positions (L1-resident)
        const float* pe1 = &g_e1[h * NN + j0];
        const float* pe2 = &g_e2[h * NN + j0];
        float e1j[8], e2j[8];
#pragma unroll
        for (int q = 0; q < 4; q++) {
            e1j[2 * q]     = __ldg(pe1 + q * 8 + t);
            e1j[2 * q + 1] = __ldg(pe1 + q * 8 + t + 4);
            e2j[2 * q]     = __ldg(pe2 + q * 8 + t);
            e2j[2 * q + 1] = __ldg(pe2 + q * 8 + t + 4);
        }

        const bool hasA = smask[it] != 0;   // warp-uniform

        uint32_t af[4][4];
#pragma unroll
        for (int q = 0; q < 4; q++) {
            float w0 = fmaxf(e1A * e1j[2 * q],     e2A * e2j[2 * q]);      // (ra, q*8+t)
            float w1 = fmaxf(e1B * e1j[2 * q],     e2B * e2j[2 * q]);      // (rb, q*8+t)
            float w2 = fmaxf(e1A * e1j[2 * q + 1], e2A * e2j[2 * q + 1]);  // (ra, q*8+t+4)
            float w3 = fmaxf(e1B * e1j[2 * q + 1], e2B * e2j[2 * q + 1]);  // (rb, q*8+t+4)
            if (hasA) {  // rare, correct path: logits + A  ->  weights * exp(A)
                float a;
                a = Amat[(size_t)(i0 + ra) * NN + j0 + q * 8 + t];
                if (a != 0.f) w0 *= __expf(a);
                a = Amat[(size_t)(i0 + rb) * NN + j0 + q * 8 + t];
                if (a != 0.f) w1 *= __expf(a);
                a = Amat[(size_t)(i0 + ra) * NN + j0 + q * 8 + t + 4];
                if (a != 0.f) w2 *= __expf(a);
                a = Amat[(size_t)(i0 + rb) * NN + j0 + q * 8 + t + 4];
                if (a != 0.f) w3 *= __expf(a);
            }
            w0 = to_tf32(w0); w1 = to_tf32(w1); w2 = to_tf32(w2); w3 = to_tf32(w3);
            dA += w0 + w2;
            dB += w1 + w3;
            af[q][0] = __float_as_uint(w0);
            af[q][1] = __float_as_uint(w1);
            af[q][2] = __float_as_uint(w2);
            af[q][3] = __float_as_uint(w3);
        }

#pragma unroll
        for (int q = 0; q < 4; q++) {
            uint32_t bf[8][2];
#pragma unroll
            for (int n = 0; n < 8; n++) {
                bf[n][0] = __float_as_uint(Vt[s][q * 8 + t][n * 8 + g]);
                bf[n][1] = __float_as_uint(Vt[s][q * 8 + t + 4][n * 8 + g]);
            }
#pragma unroll
            for (int n = 0; n < 8; n++)
                mma_tf32(acc[n], af[q], bf[n]);
        }
    }

    // denominator: reduce partials across the quad (t = 0..3)
    dA += __shfl_xor_sync(0xffffffffu, dA, 1);
    dA += __shfl_xor_sync(0xffffffffu, dA, 2);
    dB += __shfl_xor_sync(0xffffffffu, dB, 1);
    dB += __shfl_xor_sync(0xffffffffu, dB, 2);
    const float invA = 1.0f / dA;
    const float invB = 1.0f / dB;

    float* dstA = &out[(size_t)(i0 + ra) * HD + h * DD + 2 * t];
    float* dstB = &out[(size_t)(i0 + rb) * HD + h * DD + 2 * t];
#pragma unroll
    for (int n = 0; n < 8; n++) {
        *(float2*)(dstA + n * 8) = make_float2(acc[n][0] * invA, acc[n][1] * invA);
        *(float2*)(dstB + n * 8) = make_float2(acc[n][2] * invB, acc[n][3] * invB);
    }
}

// ---------------------------------------------------------------------------
extern "C" void kernel_launch(void* const* d_in, const int* in_sizes, int n_in,
                              void* d_out, int out_size)
{
    const float* inp    = (const float*)d_in[0];   // [4096, 256]
    const float* Amat   = (const float*)d_in[1];   // [4096, 4096]
    const float* W      = (const float*)d_in[2];   // [512, 256]
    const float* a_left = (const float*)d_in[3];   // [1, 8, 64]
    float* out = (float*)d_out;                    // [4096, 512]

    gemm_h_kernel<<<dim3(HD / 32, NN / 64), 128>>>(inp, W);
    amask_kernel<<<dim3(NT, 32), 256>>>(Amat);
    scores_kernel<<<(NN * NH) / 8, 256>>>(a_left);
    attn_kernel<<<dim3(NN / 64, NH), 128>>>(Amat, out);
}